// round 9
// baseline (speedup 1.0000x reference)
#include <cuda_runtime.h>
#include <cuda_fp16.h>
#include <math.h>

#define FH 50
#define FW 50
#define FC 1024
#define POOL 7

// fp16 staged feature map (5 MB). Static device array => no allocation.
__device__ __half g_fmh[FH * FW * FC];

// fp32->fp16 convert: 2 independent float4 loads (MLP=2), one uint4 store.
// Max is order-preserving under rn-conversion: pooling fp16 then widening
// equals converting the fp32 max (error <= 1 fp16 ulp, ~4.9e-4 rel).
__global__ void __launch_bounds__(256) convert_kernel(const float* __restrict__ fm) {
    const int i = blockIdx.x * 256 + threadIdx.x;   // uint4 (8-half) index
    float4 v0 = reinterpret_cast<const float4*>(fm)[2 * i];
    float4 v1 = reinterpret_cast<const float4*>(fm)[2 * i + 1];
    union { __half2 h[4]; uint4 u; } p;
    p.h[0] = __floats2half2_rn(v0.x, v0.y);
    p.h[1] = __floats2half2_rn(v0.z, v0.w);
    p.h[2] = __floats2half2_rn(v1.x, v1.y);
    p.h[3] = __floats2half2_rn(v1.z, v1.w);
    reinterpret_cast<uint4*>(g_fmh)[i] = p.u;
}

// .cg (L1-bypass) 128-bit load: feature cells have zero L1 reuse (each cell
// is read by one block, once), so skip L1 and keep it out of the replay path.
__device__ __forceinline__ uint4 ldcg_u4(const uint4* p) {
    uint4 v;
    asm volatile("ld.global.cg.v4.u32 {%0,%1,%2,%3}, [%4];"
                 : "=r"(v.x), "=r"(v.y), "=r"(v.z), "=r"(v.w) : "l"(p));
    return v;
}

// One block per (roi, bin). 128 threads, each owns one uint4 lane (8 halves)
// of the 1024-channel vector. Inner loop is the R2-proven codegen shape:
// row pointer + x-indexed size_t addressing, unroll 4.
__global__ void __launch_bounds__(128) roipool_kernel(
    const float* __restrict__ rois,  // [N,4] (y1,x1,y2,x2) normalized
    float* __restrict__ out)         // [N,7,7,1024] fp32
{
    const int bin = blockIdx.x;      // 0..48
    const int roi = blockIdx.y;
    const int by = bin / POOL;
    const int bx = bin - by * POOL;

    // ROI corners: fp32 multiply then truncating int cast (matches jnp int32 cast for >=0)
    const float4 r = reinterpret_cast<const float4*>(rois)[roi];
    const int h0 = (int)(FH * r.x);
    const int w0 = (int)(FW * r.y);
    const int h1 = (int)(FH * r.z);
    const int w1 = (int)(FW * r.w);
    const int rh = h1 - h0;
    const int rw = w1 - w0;
    const int hstep = rh / POOL;
    const int wstep = rw / POOL;

    // Bin bounds with the reference's empty-bin fixup.
    int sh = by * hstep;
    int eh = (by < POOL - 1) ? sh + hstep : rh;
    if (sh == eh) { if (eh < rh) eh += 1; else sh -= 1; }
    int sw = bx * wstep;
    int ew = (bx < POOL - 1) ? sw + wstep : rw;
    if (sw == ew) { if (ew < rw) ew += 1; else sw -= 1; }

    const int ys = max(h0 + sh, 0);
    const int ye = h0 + eh;          // <= FH
    const int xs = max(w0 + sw, 0);
    const int xe = w0 + ew;          // <= FW

    const int t = threadIdx.x;       // uint4 lane (8 halves)
    const __half2 ninf = __float2half2_rn(-INFINITY);
    __half2 a0 = ninf, a1 = ninf, a2 = ninf, a3 = ninf;

    const uint4* fm4 = reinterpret_cast<const uint4*>(g_fmh);  // FC/8 = 128 uint4 per cell
    for (int y = ys; y < ye; ++y) {
        const uint4* row = fm4 + (size_t)(y * FW) * (FC / 8) + t;
        #pragma unroll 4
        for (int x = xs; x < xe; ++x) {
            union { uint4 u; __half2 h[4]; } v;
            v.u = ldcg_u4(row + (size_t)x * (FC / 8));
            a0 = __hmax2(a0, v.h[0]);
            a1 = __hmax2(a1, v.h[1]);
            a2 = __hmax2(a2, v.h[2]);
            a3 = __hmax2(a3, v.h[3]);
        }
    }

    // fp32 output: 8 floats per thread = two float4 stores, warp-contiguous.
    const size_t o = ((size_t)roi * (POOL * POOL) + bin) * FC + (size_t)t * 8;
    float2 f0 = __half22float2(a0), f1 = __half22float2(a1);
    float2 f2 = __half22float2(a2), f3 = __half22float2(a3);
    float4* op = reinterpret_cast<float4*>(out + o);
    op[0] = make_float4(f0.x, f0.y, f1.x, f1.y);
    op[1] = make_float4(f2.x, f2.y, f3.x, f3.y);
}

extern "C" void kernel_launch(void* const* d_in, const int* in_sizes, int n_in,
                              void* d_out, int out_size) {
    const float* features = (const float*)d_in[0];  // [1,50,50,1024] fp32
    const float* rois     = (const float*)d_in[1];  // [N,4] fp32
    const int nrois = in_sizes[1] / 4;

    // 320K uint4 outputs / 256 per block = 1250 blocks.
    convert_kernel<<<FH * FW * FC / 8 / 256, 256>>>(features);

    dim3 grid(POOL * POOL, nrois);
    roipool_kernel<<<grid, 128>>>(rois, (float*)d_out);
}

// round 10
// speedup vs baseline: 1.2092x; 1.2092x over previous
#include <cuda_runtime.h>
#include <cuda_fp16.h>
#include <math.h>

#define FH 50
#define FW 50
#define FC 1024
#define POOL 7

// fp16 pyramid maps (5 MB each). Static device arrays => no allocation.
__device__ __half g_fmh[FH * FW * FC];   // F   : rn(f32)
__device__ __half g_r  [FH * FW * FC];   // R   : max over rows {y, y+1}
__device__ __half g_m2 [FH * FW * FC];   // M2  : max over {y,y+1}x{x,x+1}
// (rn is monotone and max returns one of its inputs, so
//  max(rn(a),rn(b)) == rn(max(a,b)) — fp16 pyramid == rn of fp32 pyramid.)

// Build F, R, M2 from fp32. One thread per (cell, uint4-lane): 8 channels.
// 4 source cells per thread; neighbor cells are L2-hot (4x logical reuse).
__global__ void __launch_bounds__(256) build_kernel(const float* __restrict__ fm) {
    const int i = blockIdx.x * 256 + threadIdx.x;   // 0 .. 2500*128-1
    const int cell = i >> 7;
    const int lane = i & 127;
    const int y = cell / FW;
    const int x = cell - y * FW;
    const int xp = min(x + 1, FW - 1);
    const int yp = min(y + 1, FH - 1);

    const int c00 = cell;
    const int c01 = y  * FW + xp;
    const int c10 = yp * FW + x;
    const int c11 = yp * FW + xp;

    const float4* f = reinterpret_cast<const float4*>(fm);
    const int l2 = lane * 2;
    float4 a00 = f[c00 * 256 + l2], b00 = f[c00 * 256 + l2 + 1];
    float4 a01 = f[c01 * 256 + l2], b01 = f[c01 * 256 + l2 + 1];
    float4 a10 = f[c10 * 256 + l2], b10 = f[c10 * 256 + l2 + 1];
    float4 a11 = f[c11 * 256 + l2], b11 = f[c11 * 256 + l2 + 1];

    // R = max(v00, v10); M2 = max(R, max(v01, v11)) — all in fp32, convert once.
    float4 ra = make_float4(fmaxf(a00.x, a10.x), fmaxf(a00.y, a10.y),
                            fmaxf(a00.z, a10.z), fmaxf(a00.w, a10.w));
    float4 rb = make_float4(fmaxf(b00.x, b10.x), fmaxf(b00.y, b10.y),
                            fmaxf(b00.z, b10.z), fmaxf(b00.w, b10.w));
    float4 qa = make_float4(fmaxf(a01.x, a11.x), fmaxf(a01.y, a11.y),
                            fmaxf(a01.z, a11.z), fmaxf(a01.w, a11.w));
    float4 qb = make_float4(fmaxf(b01.x, b11.x), fmaxf(b01.y, b11.y),
                            fmaxf(b01.z, b11.z), fmaxf(b01.w, b11.w));
    float4 ma = make_float4(fmaxf(ra.x, qa.x), fmaxf(ra.y, qa.y),
                            fmaxf(ra.z, qa.z), fmaxf(ra.w, qa.w));
    float4 mb = make_float4(fmaxf(rb.x, qb.x), fmaxf(rb.y, qb.y),
                            fmaxf(rb.z, qb.z), fmaxf(rb.w, qb.w));

    union { __half2 h[4]; uint4 u; } pf, pr, pm;
    pf.h[0] = __floats2half2_rn(a00.x, a00.y); pf.h[1] = __floats2half2_rn(a00.z, a00.w);
    pf.h[2] = __floats2half2_rn(b00.x, b00.y); pf.h[3] = __floats2half2_rn(b00.z, b00.w);
    pr.h[0] = __floats2half2_rn(ra.x, ra.y);   pr.h[1] = __floats2half2_rn(ra.z, ra.w);
    pr.h[2] = __floats2half2_rn(rb.x, rb.y);   pr.h[3] = __floats2half2_rn(rb.z, rb.w);
    pm.h[0] = __floats2half2_rn(ma.x, ma.y);   pm.h[1] = __floats2half2_rn(ma.z, ma.w);
    pm.h[2] = __floats2half2_rn(mb.x, mb.y);   pm.h[3] = __floats2half2_rn(mb.z, mb.w);

    reinterpret_cast<uint4*>(g_fmh)[i] = pf.u;
    reinterpret_cast<uint4*>(g_r)[i]   = pr.u;
    reinterpret_cast<uint4*>(g_m2)[i]  = pm.u;
}

// One block per (roi, bin). 128 threads = one uint4 lane (8 halves) each.
// Bin covered by overlapping 2x2-max samples (max is idempotent; clamped
// sample positions never leave the bin).
__global__ void __launch_bounds__(128) roipool_kernel(
    const float* __restrict__ rois,  // [N,4] (y1,x1,y2,x2) normalized
    float* __restrict__ out)         // [N,7,7,1024] fp32
{
    const int bin = blockIdx.x;      // 0..48
    const int roi = blockIdx.y;
    const int by = bin / POOL;
    const int bx = bin - by * POOL;

    const float4 r = reinterpret_cast<const float4*>(rois)[roi];
    const int h0 = (int)(FH * r.x);
    const int w0 = (int)(FW * r.y);
    const int h1 = (int)(FH * r.z);
    const int w1 = (int)(FW * r.w);
    const int rh = h1 - h0;
    const int rw = w1 - w0;
    const int hstep = rh / POOL;
    const int wstep = rw / POOL;

    int sh = by * hstep;
    int eh = (by < POOL - 1) ? sh + hstep : rh;
    if (sh == eh) { if (eh < rh) eh += 1; else sh -= 1; }
    int sw = bx * wstep;
    int ew = (bx < POOL - 1) ? sw + wstep : rw;
    if (sw == ew) { if (ew < rw) ew += 1; else sw -= 1; }

    const int ys = max(h0 + sh, 0);
    const int ye = h0 + eh;          // <= FH
    const int xs = max(w0 + sw, 0);
    const int xe = w0 + ew;          // <= FW
    const int h = ye - ys;
    const int w = xe - xs;

    // Select map + sampling grid.
    const uint4* base;
    int yn, xn, xstep, ylast, xlast;
    if (h >= 2) {
        yn = (h + 1) >> 1; ylast = ye - 2;
        if (w >= 2) { base = reinterpret_cast<const uint4*>(g_m2);
                      xn = (w + 1) >> 1; xstep = 2; xlast = xe - 2; }
        else        { base = reinterpret_cast<const uint4*>(g_r);
                      xn = 1; xstep = 2; xlast = xs; }
    } else {        // h == 1 (rare): single row from F
        base = reinterpret_cast<const uint4*>(g_fmh);
        yn = 1; ylast = ys; xn = w; xstep = 1; xlast = xe - 1;
    }

    const int t = threadIdx.x;       // uint4 lane (8 halves)
    const __half2 ninf = __float2half2_rn(-INFINITY);
    __half2 a0 = ninf, a1 = ninf, a2 = ninf, a3 = ninf;

    for (int iy = 0; iy < yn; ++iy) {
        const int y = min(ys + 2 * iy, ylast);
        const uint4* row = base + (size_t)(y * FW) * (FC / 8) + t;
        #pragma unroll 2
        for (int ix = 0; ix < xn; ++ix) {
            const int x = min(xs + xstep * ix, xlast);
            union { uint4 u; __half2 h[4]; } v;
            v.u = row[(size_t)x * (FC / 8)];
            a0 = __hmax2(a0, v.h[0]);
            a1 = __hmax2(a1, v.h[1]);
            a2 = __hmax2(a2, v.h[2]);
            a3 = __hmax2(a3, v.h[3]);
        }
    }

    const size_t o = ((size_t)roi * (POOL * POOL) + bin) * FC + (size_t)t * 8;
    float2 f0 = __half22float2(a0), f1 = __half22float2(a1);
    float2 f2 = __half22float2(a2), f3 = __half22float2(a3);
    float4* op = reinterpret_cast<float4*>(out + o);
    op[0] = make_float4(f0.x, f0.y, f1.x, f1.y);
    op[1] = make_float4(f2.x, f2.y, f3.x, f3.y);
}

extern "C" void kernel_launch(void* const* d_in, const int* in_sizes, int n_in,
                              void* d_out, int out_size) {
    const float* features = (const float*)d_in[0];  // [1,50,50,1024] fp32
    const float* rois     = (const float*)d_in[1];  // [N,4] fp32
    const int nrois = in_sizes[1] / 4;

    // 2500 cells x 128 lanes = 320K threads -> 1250 blocks.
    build_kernel<<<FH * FW * FC / 8 / 256, 256>>>(features);

    dim3 grid(POOL * POOL, nrois);
    roipool_kernel<<<grid, 128>>>(rois, (float*)d_out);
}